// round 9
// baseline (speedup 1.0000x reference)
#include <cuda_runtime.h>

// RoiAlign (TF crop_and_resize, bilinear), fixed problem shape:
//   features: [B=2, H=64, W=64, C=256] fp32
//   rois:     [B=2, N=2000, 4] fp32 normalized (y1,x1,y2,x2)
//   out:      [B, N, 7, 7, C] fp32
constexpr int H  = 64;
constexpr int W  = 64;
constexpr int C  = 256;
constexpr int PH = 7;
constexpr int PW = 7;
constexpr int CV = C / 4;   // 64 float4 per pixel

// grid = (PH, N, B), block = (32, PW).
// One warp handles one output pixel (b, n, py, px): lane covers c4 = lane
// and c4 = lane + 32 (two float4 = 8 channels per thread).
__global__ void __launch_bounds__(32 * PW) roialign_kernel(
    const float4* __restrict__ feat,   // [B, H, W, CV]
    const float4* __restrict__ rois,   // [B*N] boxes as float4
    float4*       __restrict__ out,    // [B, N, PH, PW, CV]
    int N)
{
    const int py   = blockIdx.x;     // 0..6
    const int n    = blockIdx.y;     // 0..N-1
    const int b    = blockIdx.z;     // 0..1
    const int px   = threadIdx.y;    // 0..6
    const int lane = threadIdx.x;    // 0..31

    // Box (uniform per block row; single 16B load, broadcast)
    float4 box = rois[(size_t)b * N + n];   // (y1, x1, y2, x2)

    float fy = (float)py / (float)(PH - 1);
    float fx = (float)px / (float)(PW - 1);
    float ys = (box.x + fy * (box.z - box.x)) * (float)(H - 1);
    float xs = (box.y + fx * (box.w - box.y)) * (float)(W - 1);

    float y0f = fminf(fmaxf(floorf(ys), 0.0f), (float)(H - 1));
    float x0f = fminf(fmaxf(floorf(xs), 0.0f), (float)(W - 1));
    int   y0  = (int)y0f;
    int   x0  = (int)x0f;
    int   dy  = (y0 + 1 <= H - 1) ? W * CV : 0;   // row step (or clamp)
    int   dx  = (x0 + 1 <= W - 1) ? CV : 0;       // col step (or clamp)

    float wy  = ys - y0f;
    float wx  = xs - x0f;
    float oy  = 1.0f - wy;
    float ox  = 1.0f - wx;
    float w00 = oy * ox;
    float w01 = oy * wx;
    float w10 = wy * ox;
    float w11 = wy * wx;

    const float4* p00 = feat + ((size_t)b * H * W + y0 * W + x0) * CV + lane;

    // 8 independent loads, front-batched for MLP; +32 variants are
    // immediate-offset loads off the same address registers.
    float4 f00a = p00[0];
    float4 f01a = p00[dx];
    float4 f10a = p00[dy];
    float4 f11a = p00[dy + dx];
    float4 f00b = p00[32];
    float4 f01b = p00[dx + 32];
    float4 f10b = p00[dy + 32];
    float4 f11b = p00[dy + dx + 32];

    float4 ra, rb;
    ra.x = fmaf(f11a.x, w11, fmaf(f10a.x, w10, fmaf(f01a.x, w01, f00a.x * w00)));
    ra.y = fmaf(f11a.y, w11, fmaf(f10a.y, w10, fmaf(f01a.y, w01, f00a.y * w00)));
    ra.z = fmaf(f11a.z, w11, fmaf(f10a.z, w10, fmaf(f01a.z, w01, f00a.z * w00)));
    ra.w = fmaf(f11a.w, w11, fmaf(f10a.w, w10, fmaf(f01a.w, w01, f00a.w * w00)));
    rb.x = fmaf(f11b.x, w11, fmaf(f10b.x, w10, fmaf(f01b.x, w01, f00b.x * w00)));
    rb.y = fmaf(f11b.y, w11, fmaf(f10b.y, w10, fmaf(f01b.y, w01, f00b.y * w00)));
    rb.z = fmaf(f11b.z, w11, fmaf(f10b.z, w10, fmaf(f01b.z, w01, f00b.z * w00)));
    rb.w = fmaf(f11b.w, w11, fmaf(f10b.w, w10, fmaf(f01b.w, w01, f00b.w * w00)));

    float4* o = out + ((((size_t)b * N + n) * PH + py) * PW + px) * CV + lane;
    o[0]  = ra;
    o[32] = rb;
}

extern "C" void kernel_launch(void* const* d_in, const int* in_sizes, int n_in,
                              void* d_out, int out_size)
{
    const float4* features = (const float4*)d_in[0];
    const float4* rois     = (const float4*)d_in[1];
    float4* out            = (float4*)d_out;

    const int B = 2;
    int N = in_sizes[1] / (B * 4);     // 2000

    dim3 grid(PH, N, B);
    dim3 block(32, PW);
    roialign_kernel<<<grid, block>>>(features, rois, out, N);
}

// round 10
// speedup vs baseline: 1.0303x; 1.0303x over previous
#include <cuda_runtime.h>

// RoiAlign (TF crop_and_resize, bilinear), fixed problem shape:
//   features: [B=2, H=64, W=64, C=256] fp32
//   rois:     [B=2, N=2000, 4] fp32 normalized (y1,x1,y2,x2)
//   out:      [B, N, 7, 7, C] fp32
constexpr int H  = 64;
constexpr int W  = 64;
constexpr int C  = 256;
constexpr int PH = 7;
constexpr int PW = 7;
constexpr int CV = C / 4;   // 64 float4 per pixel

// grid = (PH, N, B), block = (32, PW).
// One warp handles one output pixel (b, n, py, px): lane covers c4 = lane
// and c4 = lane + 32 (two float4 = 8 channels per thread).
__global__ void __launch_bounds__(32 * PW) roialign_kernel(
    const float4* __restrict__ feat,   // [B, H, W, CV]
    const float4* __restrict__ rois,   // [B*N] boxes as float4
    float4*       __restrict__ out,    // [B, N, PH, PW, CV]
    int N)
{
    const int py   = blockIdx.x;     // 0..6
    const int n    = blockIdx.y;     // 0..N-1
    const int b    = blockIdx.z;     // 0..1
    const int px   = threadIdx.y;    // 0..6
    const int lane = threadIdx.x;    // 0..31

    // Box (uniform per block row; single 16B load, broadcast)
    float4 box = rois[(size_t)b * N + n];   // (y1, x1, y2, x2)

    float fy = (float)py / (float)(PH - 1);
    float fx = (float)px / (float)(PW - 1);
    float ys = (box.x + fy * (box.z - box.x)) * (float)(H - 1);
    float xs = (box.y + fx * (box.w - box.y)) * (float)(W - 1);

    float y0f = fminf(fmaxf(floorf(ys), 0.0f), (float)(H - 1));
    float x0f = fminf(fmaxf(floorf(xs), 0.0f), (float)(W - 1));
    int   y0  = (int)y0f;
    int   x0  = (int)x0f;
    int   dy  = (y0 + 1 <= H - 1) ? W * CV : 0;   // row step (or clamp)
    int   dx  = (x0 + 1 <= W - 1) ? CV : 0;       // col step (or clamp)

    float wy  = ys - y0f;
    float wx  = xs - x0f;
    float oy  = 1.0f - wy;
    float ox  = 1.0f - wx;
    float w00 = oy * ox;
    float w01 = oy * wx;
    float w10 = wy * ox;
    float w11 = wy * wx;

    const float4* p00 = feat + ((size_t)b * H * W + y0 * W + x0) * CV + lane;

    // 8 independent loads, front-batched for MLP; +32 variants are
    // immediate-offset loads off the same address registers.
    float4 f00a = p00[0];
    float4 f01a = p00[dx];
    float4 f10a = p00[dy];
    float4 f11a = p00[dy + dx];
    float4 f00b = p00[32];
    float4 f01b = p00[dx + 32];
    float4 f10b = p00[dy + 32];
    float4 f11b = p00[dy + dx + 32];

    float4 ra, rb;
    ra.x = fmaf(f11a.x, w11, fmaf(f10a.x, w10, fmaf(f01a.x, w01, f00a.x * w00)));
    ra.y = fmaf(f11a.y, w11, fmaf(f10a.y, w10, fmaf(f01a.y, w01, f00a.y * w00)));
    ra.z = fmaf(f11a.z, w11, fmaf(f10a.z, w10, fmaf(f01a.z, w01, f00a.z * w00)));
    ra.w = fmaf(f11a.w, w11, fmaf(f10a.w, w10, fmaf(f01a.w, w01, f00a.w * w00)));
    rb.x = fmaf(f11b.x, w11, fmaf(f10b.x, w10, fmaf(f01b.x, w01, f00b.x * w00)));
    rb.y = fmaf(f11b.y, w11, fmaf(f10b.y, w10, fmaf(f01b.y, w01, f00b.y * w00)));
    rb.z = fmaf(f11b.z, w11, fmaf(f10b.z, w10, fmaf(f01b.z, w01, f00b.z * w00)));
    rb.w = fmaf(f11b.w, w11, fmaf(f10b.w, w10, fmaf(f01b.w, w01, f00b.w * w00)));

    float4* o = out + ((((size_t)b * N + n) * PH + py) * PW + px) * CV + lane;
    o[0]  = ra;
    o[32] = rb;
}

extern "C" void kernel_launch(void* const* d_in, const int* in_sizes, int n_in,
                              void* d_out, int out_size)
{
    const float4* features = (const float4*)d_in[0];
    const float4* rois     = (const float4*)d_in[1];
    float4* out            = (float4*)d_out;

    const int B = 2;
    int N = in_sizes[1] / (B * 4);     // 2000

    dim3 grid(PH, N, B);
    dim3 block(32, PW);
    roialign_kernel<<<grid, block>>>(features, rois, out, N);
}